// round 8
// baseline (speedup 1.0000x reference)
#include <cuda_runtime.h>
#include <cstdint>

// LBFGS two-loop recursion, fully Gram-based, 3-stage pipeline.
//   K1: E[i][j]=s_i.y_j, F[i][j]=y_i.y_j, w[i]=s_i.frc, u[i]=y_i.frc
//       (reads S,Y,frc ONCE; f32x2 4x4 register-tile Gram)
//   K2: per-batch warp solve:
//       a_i = (-w_i - sum_{j>i} a_j E[i][j]) / E[i][i],  r_i = 1/E[i][i]
//       g   = E[31][31]/F[31][31]
//       v_i = -u_i - sum_j a_j F[i][j]          (v = y_i . qb, qb never formed)
//       c_i = a_i - r_i (g v_i + sum_{j<i} c_j E[j][i])
//   K3: out = g*frc + sum_j (g a_j) y_j - sum_i c_i s_i   (reads S,Y,frc once)
// Total DRAM: 2x(S+Y) + small = ~260MB, all at full chip width; no serial
// chain over the 2MB carry, no qb intermediate.

#define MM 32
#define BB 64
#define DD 8192

#define CH1 256
#define NCH1 (DD / CH1)                       // 32
#define ST1 260                               // padded smem row stride
#define K1_SMEM ((2 * 32 * ST1 + CH1) * 4)    // 67584 B

#define CH3 1024
#define NCH3 (DD / CH3)                       // 8

typedef unsigned long long u64;

// ---------------- device scratch (static: no allocation) ----------------
__device__ float gE[BB * MM * MM];
__device__ float gF[BB * MM * MM];
__device__ float gw[BB * MM];
__device__ float gu[BB * MM];
__device__ float gya[BB * MM];   // g * a_j
__device__ float gcc[BB * MM];   // c_i
__device__ float gg[BB];         // g

// ---------------- f32x2 helpers ----------------
__device__ __forceinline__ u64 pk2(float a, float b) {
    u64 r; asm("mov.b64 %0, {%1,%2};" : "=l"(r) : "f"(a), "f"(b)); return r;
}
__device__ __forceinline__ float2 upk2(u64 v) {
    float2 f; asm("mov.b64 {%0,%1}, %2;" : "=f"(f.x), "=f"(f.y) : "l"(v)); return f;
}
__device__ __forceinline__ u64 fma2(u64 a, u64 b, u64 c) {
    u64 d; asm("fma.rn.f32x2 %0, %1, %2, %3;" : "=l"(d) : "l"(a), "l"(b), "l"(c)); return d;
}
__device__ __forceinline__ float dot4(float4 a, float4 b) {
    return a.x * b.x + a.y * b.y + a.z * b.z + a.w * b.w;
}

// ---------------- K0: zero accumulators ----------------
__global__ void k0_zero() {
    const int b = blockIdx.x;
    const int t = threadIdx.x;           // 1024 threads
    gE[b * (MM * MM) + t] = 0.0f;
    gF[b * (MM * MM) + t] = 0.0f;
    if (t < MM) { gw[b * MM + t] = 0.0f; gu[b * MM + t] = 0.0f; }
}

// ---------------- K1: Gram (E, F, w, u) ----------------
__global__ __launch_bounds__(256, 2)
void k1_gram(const float* __restrict__ S, const float* __restrict__ Y,
             const float* __restrict__ FRC) {
    extern __shared__ __align__(16) float smem[];
    float* sS = smem;                 // 32 x ST1
    float* sY = smem + 32 * ST1;      // 32 x ST1
    float* sF = smem + 64 * ST1;      // CH1

    const int b  = blockIdx.x >> 5;
    const int ch = blockIdx.x & 31;
    const int tid = threadIdx.x;

    // load S,Y 32x256 tiles (coalesced float4) into padded smem
#pragma unroll
    for (int r = 0; r < 8; ++r) {
        const int idx = r * 256 + tid;
        const int row = idx >> 6;          // 64 float4 per row
        const int c4  = idx & 63;
        const size_t g = ((size_t)row * BB + b) * DD + (size_t)ch * CH1 + c4 * 4;
        *(float4*)&sS[row * ST1 + c4 * 4] = *(const float4*)(S + g);
        *(float4*)&sY[row * ST1 + c4 * 4] = *(const float4*)(Y + g);
    }
    if (tid < 64) {
        *(float4*)&sF[tid * 4] =
            *(const float4*)(FRC + (size_t)b * DD + (size_t)ch * CH1 + tid * 4);
    }
    __syncthreads();

    // 4x4 register tile per thread: rows i0+8k, cols j0+8l, d-quarter dq
    const int tile = tid & 63;
    const int dq   = tid >> 6;
    const int i0   = tile >> 3;          // 0..7
    const int j0   = tile & 7;           // 0..7
    const int dbase = dq * 64;

    // ---- pass A: E = S . Y^T ----
    {
        u64 acc[16];
#pragma unroll
        for (int n = 0; n < 16; ++n) acc[n] = 0ull;
#pragma unroll
        for (int d4 = 0; d4 < 16; ++d4) {
            const int c = dbase + d4 * 4;
            ulonglong2 su[4], yu[4];
#pragma unroll
            for (int k = 0; k < 4; ++k)
                su[k] = *(const ulonglong2*)&sS[(i0 + 8 * k) * ST1 + c];
#pragma unroll
            for (int l = 0; l < 4; ++l)
                yu[l] = *(const ulonglong2*)&sY[(j0 + 8 * l) * ST1 + c];
#pragma unroll
            for (int k = 0; k < 4; ++k)
#pragma unroll
                for (int l = 0; l < 4; ++l) {
                    acc[k * 4 + l] = fma2(su[k].x, yu[l].x, acc[k * 4 + l]);
                    acc[k * 4 + l] = fma2(su[k].y, yu[l].y, acc[k * 4 + l]);
                }
        }
#pragma unroll
        for (int k = 0; k < 4; ++k)
#pragma unroll
            for (int l = 0; l < 4; ++l) {
                float2 p = upk2(acc[k * 4 + l]);
                atomicAdd(&gE[b * (MM * MM) + (i0 + 8 * k) * MM + (j0 + 8 * l)],
                          p.x + p.y);
            }
    }

    // ---- pass B: F = Y . Y^T ----
    {
        u64 acc[16];
#pragma unroll
        for (int n = 0; n < 16; ++n) acc[n] = 0ull;
#pragma unroll
        for (int d4 = 0; d4 < 16; ++d4) {
            const int c = dbase + d4 * 4;
            ulonglong2 su[4], yu[4];
#pragma unroll
            for (int k = 0; k < 4; ++k)
                su[k] = *(const ulonglong2*)&sY[(i0 + 8 * k) * ST1 + c];
#pragma unroll
            for (int l = 0; l < 4; ++l)
                yu[l] = *(const ulonglong2*)&sY[(j0 + 8 * l) * ST1 + c];
#pragma unroll
            for (int k = 0; k < 4; ++k)
#pragma unroll
                for (int l = 0; l < 4; ++l) {
                    acc[k * 4 + l] = fma2(su[k].x, yu[l].x, acc[k * 4 + l]);
                    acc[k * 4 + l] = fma2(su[k].y, yu[l].y, acc[k * 4 + l]);
                }
        }
#pragma unroll
        for (int k = 0; k < 4; ++k)
#pragma unroll
            for (int l = 0; l < 4; ++l) {
                float2 p = upk2(acc[k * 4 + l]);
                atomicAdd(&gF[b * (MM * MM) + (i0 + 8 * k) * MM + (j0 + 8 * l)],
                          p.x + p.y);
            }
    }

    // ---- w[i] = s_i.frc, u[i] = y_i.frc (warp wrp: rows wrp, wrp+8, ...) ----
    const int wrp  = tid >> 5;
    const int lane = tid & 31;
#pragma unroll
    for (int m = 0; m < 4; ++m) {
        const int i = wrp + 8 * m;
        float4 f0 = *(const float4*)&sF[lane * 8];
        float4 f1 = *(const float4*)&sF[lane * 8 + 4];
        float4 a0 = *(const float4*)&sS[i * ST1 + lane * 8];
        float4 a1 = *(const float4*)&sS[i * ST1 + lane * 8 + 4];
        float4 b0 = *(const float4*)&sY[i * ST1 + lane * 8];
        float4 b1 = *(const float4*)&sY[i * ST1 + lane * 8 + 4];
        float tw = dot4(a0, f0) + dot4(a1, f1);
        float tu = dot4(b0, f0) + dot4(b1, f1);
#pragma unroll
        for (int off = 16; off > 0; off >>= 1) {
            tw += __shfl_xor_sync(0xffffffffu, tw, off);
            tu += __shfl_xor_sync(0xffffffffu, tu, off);
        }
        if (lane == 0) {
            atomicAdd(&gw[b * MM + i], tw);
            atomicAdd(&gu[b * MM + i], tu);
        }
    }
}

// ---------------- K2: full scalar solve — one warp per batch ----------------
__global__ void k2_solve(void) {
    const int b = blockIdx.x;
    const int j = threadIdx.x;   // 32 threads
    const float* Eb = gE + b * (MM * MM);
    const float* Fb = gF + b * (MM * MM);

    // phase 1: backward solve for a (thread j holds E column j)
    float ecol[MM];
#pragma unroll
    for (int i = 0; i < MM; ++i) ecol[i] = Eb[i * MM + j];
    const float w_own = gw[b * MM + j];

    float a_own = 0.0f, r_own = 0.0f;
#pragma unroll
    for (int ii = 0; ii < MM; ++ii) {
        const int i = MM - 1 - ii;
        float contrib = (j > i) ? a_own * ecol[i] : 0.0f;
#pragma unroll
        for (int off = 16; off > 0; off >>= 1)
            contrib += __shfl_xor_sync(0xffffffffu, contrib, off);
        const float ediag = __shfl_sync(0xffffffffu, ecol[i], i);
        const float wi    = __shfl_sync(0xffffffffu, w_own, i);
        const float ai    = (-wi - contrib) / ediag;
        if (j == i) { a_own = ai; r_own = 1.0f / ediag; }
    }

    const float g = Eb[(MM - 1) * MM + (MM - 1)] / Fb[(MM - 1) * MM + (MM - 1)];

    // phase 2: v_j = -u_j - sum_i a_i F[j][i]  (F row j, contiguous)
    float v_own = -gu[b * MM + j];
    {
        const float4* frow4 = (const float4*)(Fb + j * MM);
#pragma unroll
        for (int q = 0; q < 8; ++q) {
            float4 fv = frow4[q];
            v_own -= __shfl_sync(0xffffffffu, a_own, q * 4 + 0) * fv.x;
            v_own -= __shfl_sync(0xffffffffu, a_own, q * 4 + 1) * fv.y;
            v_own -= __shfl_sync(0xffffffffu, a_own, q * 4 + 2) * fv.z;
            v_own -= __shfl_sync(0xffffffffu, a_own, q * 4 + 3) * fv.w;
        }
    }

    // phase 3: forward solve for c (thread j holds E row j)
    float erow[MM];
    {
        const float4* row4 = (const float4*)(Eb + j * MM);
#pragma unroll
        for (int q = 0; q < 8; ++q) {
            float4 v = row4[q];
            erow[q * 4 + 0] = v.x; erow[q * 4 + 1] = v.y;
            erow[q * 4 + 2] = v.z; erow[q * 4 + 3] = v.w;
        }
    }
    float c_own = 0.0f;
#pragma unroll
    for (int i = 0; i < MM; ++i) {
        float contrib = (j < i) ? c_own * erow[i] : 0.0f;
#pragma unroll
        for (int off = 16; off > 0; off >>= 1)
            contrib += __shfl_xor_sync(0xffffffffu, contrib, off);
        const float ri = __shfl_sync(0xffffffffu, r_own, i);
        const float ai = __shfl_sync(0xffffffffu, a_own, i);
        const float vi = __shfl_sync(0xffffffffu, v_own, i);
        const float ci = ai - ri * (g * vi + contrib);
        if (j == i) c_own = ci;
    }

    gya[b * MM + j] = g * a_own;
    gcc[b * MM + j] = c_own;
    if (j == 0) gg[b] = g;
}

// ---------------- K3: out = g frc + sum (g a_j) y_j - sum c_i s_i --------
__global__ __launch_bounds__(256)
void k3_out(const float* __restrict__ S, const float* __restrict__ Y,
            const float* __restrict__ FRC, float* __restrict__ OUT) {
    __shared__ float sya[MM];
    __shared__ float scc[MM];
    __shared__ float sg[1];

    const int b  = blockIdx.x >> 3;
    const int ch = blockIdx.x & 7;
    const int tid = threadIdx.x;

    if (tid < MM) { sya[tid] = gya[b * MM + tid]; scc[tid] = gcc[b * MM + tid]; }
    if (tid == MM) sg[0] = gg[b];
    __syncthreads();

    const size_t d0 = (size_t)ch * CH3 + tid * 4;
    const float g = sg[0];
    float4 f = *(const float4*)(FRC + (size_t)b * DD + d0);
    u64 acc0 = pk2(g * f.x, g * f.y);
    u64 acc1 = pk2(g * f.z, g * f.w);

#pragma unroll
    for (int j = 0; j < MM; ++j) {
        ulonglong2 yv = *(const ulonglong2*)(Y + ((size_t)j * BB + b) * DD + d0);
        const float cv = sya[j];
        const u64 cc = pk2(cv, cv);
        acc0 = fma2(cc, yv.x, acc0);
        acc1 = fma2(cc, yv.y, acc1);
    }
#pragma unroll
    for (int i = 0; i < MM; ++i) {
        ulonglong2 sv = *(const ulonglong2*)(S + ((size_t)i * BB + b) * DD + d0);
        const float cv = -scc[i];
        const u64 cc = pk2(cv, cv);
        acc0 = fma2(cc, sv.x, acc0);
        acc1 = fma2(cc, sv.y, acc1);
    }

    float2 o0 = upk2(acc0), o1 = upk2(acc1);
    float4 o; o.x = o0.x; o.y = o0.y; o.z = o1.x; o.w = o1.y;
    *(float4*)(OUT + (size_t)b * DD + d0) = o;
}

// ---------------- launch ----------------
extern "C" void kernel_launch(void* const* d_in, const int* in_sizes, int n_in,
                              void* d_out, int out_size) {
    const float* S   = (const float*)d_in[0];  // (M, B, D)
    const float* Y   = (const float*)d_in[1];  // (M, B, D)
    const float* FRC = (const float*)d_in[2];  // (B, D)
    float* OUT = (float*)d_out;                // (B, D)

    static bool attr_set = false;
    if (!attr_set) {
        cudaFuncSetAttribute(k1_gram,
                             cudaFuncAttributeMaxDynamicSharedMemorySize,
                             K1_SMEM);
        attr_set = true;
    }

    k0_zero<<<BB, MM * MM>>>();
    k1_gram<<<BB * NCH1, 256, K1_SMEM>>>(S, Y, FRC);
    k2_solve<<<BB, 32>>>();
    k3_out<<<BB * NCH3, 256>>>(S, Y, FRC, OUT);
}

// round 10
// speedup vs baseline: 2.3495x; 2.3495x over previous
#include <cuda_runtime.h>
#include <cstdint>

// LBFGS two-loop recursion, Gram-based, 3 launches, ZERO atomics.
//   K1: fused Gram partials per (batch, D-group):
//       Ep[g] = S.Y^T, Fp[g] = Y.Y^T over K=1024 slice; wp,up = (S|Y).frc
//       written with plain STG (each CTA owns its slice).
//   K2: sum 8 partials -> E,F in smem; warp solve for a, r, g, v, c;
//       emit gya = g*a, gcc = c, gg = g.
//   K3: out = g*frc + sum_j (g a_j) y_j - sum_i c_i s_i  (proven 25us @70% DRAM)
// R9 bugfix: partial-writeback loop is 4 iterations (1024 elems / 256 thr),
// not 8 -- the 8-iteration version wrote 1KB past each Gram tile (OOB).

#define MM 32
#define BB 64
#define DD 8192

#define NG 8                          // D-groups
#define KG (DD / NG)                  // 1024 floats per group
#define SUB 256                       // sub-chunk (smem tile width)
#define NSUB (KG / SUB)               // 4
#define ST1 260                       // padded smem row stride (floats)
#define K1_SMEM ((2 * 32 * ST1 + SUB + 4 * 64 * 16) * 4)  // tiles + frc + red

#define CH3 1024
#define NCH3 (DD / CH3)               // 8

typedef unsigned long long u64;

// ---------------- device scratch (static: no allocation) ----------------
__device__ float gEp[NG * BB * MM * MM];   // per-group E partials
__device__ float gFp[NG * BB * MM * MM];   // per-group F partials
__device__ float gwp[NG * BB * MM];
__device__ float gup[NG * BB * MM];
__device__ float gya[BB * MM];
__device__ float gcc[BB * MM];
__device__ float gg[BB];

// ---------------- f32x2 helpers ----------------
__device__ __forceinline__ u64 pk2(float a, float b) {
    u64 r; asm("mov.b64 %0, {%1,%2};" : "=l"(r) : "f"(a), "f"(b)); return r;
}
__device__ __forceinline__ float2 upk2(u64 v) {
    float2 f; asm("mov.b64 {%0,%1}, %2;" : "=f"(f.x), "=f"(f.y) : "l"(v)); return f;
}
__device__ __forceinline__ u64 fma2(u64 a, u64 b, u64 c) {
    u64 d; asm("fma.rn.f32x2 %0, %1, %2, %3;" : "=l"(d) : "l"(a), "l"(b), "l"(c)); return d;
}
__device__ __forceinline__ float dot4(float4 a, float4 b) {
    return a.x * b.x + a.y * b.y + a.z * b.z + a.w * b.w;
}

// ---------------- K1: fused Gram partials ----------------
__global__ __launch_bounds__(256, 2)
void k1_gram(const float* __restrict__ S, const float* __restrict__ Y,
             const float* __restrict__ FRC) {
    extern __shared__ __align__(16) float smem[];
    float* sS  = smem;                  // 32 x ST1
    float* sY  = smem + 32 * ST1;       // 32 x ST1
    float* sFr = smem + 64 * ST1;       // SUB floats
    float* sRed = sFr + SUB;            // 4 dq x 64 tiles x 16 vals

    const int b   = blockIdx.x >> 3;
    const int grp = blockIdx.x & 7;
    const int tid = threadIdx.x;

    const int tile = tid & 63;
    const int dq   = tid >> 6;
    const int i0   = tile >> 3;
    const int j0   = tile & 7;
    const int dbase = dq * 64;

    u64 accE[16], accF[16];
#pragma unroll
    for (int n = 0; n < 16; ++n) { accE[n] = 0ull; accF[n] = 0ull; }

    const int wrp  = tid >> 5;
    const int lane = tid & 31;
    float tw[4] = {0.f, 0.f, 0.f, 0.f};
    float tu[4] = {0.f, 0.f, 0.f, 0.f};

#pragma unroll 1
    for (int sub = 0; sub < NSUB; ++sub) {
        const size_t cbase = (size_t)grp * KG + (size_t)sub * SUB;

        // load 32x256 S,Y tiles (coalesced float4) + frc chunk
#pragma unroll
        for (int r = 0; r < 8; ++r) {
            const int idx = r * 256 + tid;
            const int row = idx >> 6;
            const int c4  = idx & 63;
            const size_t g = ((size_t)row * BB + b) * DD + cbase + c4 * 4;
            *(float4*)&sS[row * ST1 + c4 * 4] = *(const float4*)(S + g);
            *(float4*)&sY[row * ST1 + c4 * 4] = *(const float4*)(Y + g);
        }
        if (tid < 64)
            *(float4*)&sFr[tid * 4] =
                *(const float4*)(FRC + (size_t)b * DD + cbase + tid * 4);
        __syncthreads();

        // fused E (S.Y^T) and F (Y.Y^T) accumulation
#pragma unroll
        for (int d4 = 0; d4 < 16; ++d4) {
            const int c = dbase + d4 * 4;
            ulonglong2 su[4], zu[4], yu[4];
#pragma unroll
            for (int k = 0; k < 4; ++k) {
                su[k] = *(const ulonglong2*)&sS[(i0 + 8 * k) * ST1 + c];
                zu[k] = *(const ulonglong2*)&sY[(i0 + 8 * k) * ST1 + c];
            }
#pragma unroll
            for (int l = 0; l < 4; ++l)
                yu[l] = *(const ulonglong2*)&sY[(j0 + 8 * l) * ST1 + c];
#pragma unroll
            for (int k = 0; k < 4; ++k)
#pragma unroll
                for (int l = 0; l < 4; ++l) {
                    accE[k * 4 + l] = fma2(su[k].x, yu[l].x, accE[k * 4 + l]);
                    accE[k * 4 + l] = fma2(su[k].y, yu[l].y, accE[k * 4 + l]);
                    accF[k * 4 + l] = fma2(zu[k].x, yu[l].x, accF[k * 4 + l]);
                    accF[k * 4 + l] = fma2(zu[k].y, yu[l].y, accF[k * 4 + l]);
                }
        }

        // w/u partial dots (warp wrp handles rows wrp, wrp+8, +16, +24)
#pragma unroll
        for (int m = 0; m < 4; ++m) {
            const int i = wrp + 8 * m;
            float4 f0 = *(const float4*)&sFr[lane * 8];
            float4 f1 = *(const float4*)&sFr[lane * 8 + 4];
            float4 a0 = *(const float4*)&sS[i * ST1 + lane * 8];
            float4 a1 = *(const float4*)&sS[i * ST1 + lane * 8 + 4];
            float4 b0 = *(const float4*)&sY[i * ST1 + lane * 8];
            float4 b1 = *(const float4*)&sY[i * ST1 + lane * 8 + 4];
            tw[m] += dot4(a0, f0) + dot4(a1, f1);
            tu[m] += dot4(b0, f0) + dot4(b1, f1);
        }
        __syncthreads();   // tiles consumed; safe to overwrite next sub-chunk
    }

    // ---- cross-dq reduction in smem, then plain STG of partials ----
    // 32x32 = 1024 elements, 256 threads -> 4 elements per thread (NOT 8).
    {
        float* myE = sRed + (dq * 64 + tile) * 16;
#pragma unroll
        for (int n = 0; n < 16; ++n) {
            float2 p = upk2(accE[n]);
            myE[n] = p.x + p.y;
        }
    }
    __syncthreads();
    {
        float* outE = gEp + ((size_t)grp * BB + b) * (MM * MM);
#pragma unroll
        for (int e = 0; e < 4; ++e) {
            const int el = tid + e * 256;           // element (I,J), el < 1024
            const int I = el >> 5, J = el & 31;
            const int ti = (I & 7) * 8 + (J & 7);
            const int kl = (I >> 3) * 4 + (J >> 3);
            float v = sRed[(0 * 64 + ti) * 16 + kl] + sRed[(1 * 64 + ti) * 16 + kl]
                    + sRed[(2 * 64 + ti) * 16 + kl] + sRed[(3 * 64 + ti) * 16 + kl];
            outE[el] = v;
        }
    }
    __syncthreads();
    {
        float* myF = sRed + (dq * 64 + tile) * 16;
#pragma unroll
        for (int n = 0; n < 16; ++n) {
            float2 p = upk2(accF[n]);
            myF[n] = p.x + p.y;
        }
    }
    __syncthreads();
    {
        float* outF = gFp + ((size_t)grp * BB + b) * (MM * MM);
#pragma unroll
        for (int e = 0; e < 4; ++e) {
            const int el = tid + e * 256;
            const int I = el >> 5, J = el & 31;
            const int ti = (I & 7) * 8 + (J & 7);
            const int kl = (I >> 3) * 4 + (J >> 3);
            float v = sRed[(0 * 64 + ti) * 16 + kl] + sRed[(1 * 64 + ti) * 16 + kl]
                    + sRed[(2 * 64 + ti) * 16 + kl] + sRed[(3 * 64 + ti) * 16 + kl];
            outF[el] = v;
        }
    }

    // w/u: shfl-reduce per warp, lane0 writes its 4 rows' partials
#pragma unroll
    for (int m = 0; m < 4; ++m) {
#pragma unroll
        for (int off = 16; off > 0; off >>= 1) {
            tw[m] += __shfl_xor_sync(0xffffffffu, tw[m], off);
            tu[m] += __shfl_xor_sync(0xffffffffu, tu[m], off);
        }
    }
    if (lane == 0) {
        float* ow = gwp + ((size_t)grp * BB + b) * MM;
        float* ou = gup + ((size_t)grp * BB + b) * MM;
#pragma unroll
        for (int m = 0; m < 4; ++m) {
            ow[wrp + 8 * m] = tw[m];
            ou[wrp + 8 * m] = tu[m];
        }
    }
}

// ---------------- K2: reduce partials + full scalar solve ----------------
__global__ __launch_bounds__(256)
void k2_solve(void) {
    __shared__ float sE[MM * MM];
    __shared__ float sF[MM * MM];

    const int b   = blockIdx.x;
    const int tid = threadIdx.x;

    // sum 8 group partials (256 threads x 1 float4 each per array)
    {
        float4 aE = make_float4(0.f, 0.f, 0.f, 0.f);
        float4 aF = aE;
#pragma unroll
        for (int g = 0; g < NG; ++g) {
            const size_t base4 = ((size_t)g * BB + b) * (MM * MM / 4) + tid;
            float4 e = ((const float4*)gEp)[base4];
            float4 f = ((const float4*)gFp)[base4];
            aE.x += e.x; aE.y += e.y; aE.z += e.z; aE.w += e.w;
            aF.x += f.x; aF.y += f.y; aF.z += f.z; aF.w += f.w;
        }
        ((float4*)sE)[tid] = aE;
        ((float4*)sF)[tid] = aF;
    }
    __syncthreads();

    if (tid >= 32) return;
    const int j = tid;

    float w_own = 0.f, u_own = 0.f;
#pragma unroll
    for (int g = 0; g < NG; ++g) {
        w_own += gwp[((size_t)g * BB + b) * MM + j];
        u_own += gup[((size_t)g * BB + b) * MM + j];
    }

    // phase 1: backward solve for a (thread j holds E column j)
    float ecol[MM];
#pragma unroll
    for (int i = 0; i < MM; ++i) ecol[i] = sE[i * MM + j];

    float a_own = 0.0f, r_own = 0.0f;
#pragma unroll
    for (int ii = 0; ii < MM; ++ii) {
        const int i = MM - 1 - ii;
        float contrib = (j > i) ? a_own * ecol[i] : 0.0f;
#pragma unroll
        for (int off = 16; off > 0; off >>= 1)
            contrib += __shfl_xor_sync(0xffffffffu, contrib, off);
        const float ediag = __shfl_sync(0xffffffffu, ecol[i], i);
        const float wi    = __shfl_sync(0xffffffffu, w_own, i);
        const float ai    = (-wi - contrib) / ediag;
        if (j == i) { a_own = ai; r_own = 1.0f / ediag; }
    }

    const float g = sE[(MM - 1) * MM + (MM - 1)] / sF[(MM - 1) * MM + (MM - 1)];

    // phase 2: v_j = -u_j - sum_i a_i F[j][i]
    float v_own = -u_own;
#pragma unroll
    for (int q = 0; q < 8; ++q) {
        float4 fv = *(const float4*)&sF[j * MM + q * 4];
        v_own -= __shfl_sync(0xffffffffu, a_own, q * 4 + 0) * fv.x;
        v_own -= __shfl_sync(0xffffffffu, a_own, q * 4 + 1) * fv.y;
        v_own -= __shfl_sync(0xffffffffu, a_own, q * 4 + 2) * fv.z;
        v_own -= __shfl_sync(0xffffffffu, a_own, q * 4 + 3) * fv.w;
    }

    // phase 3: forward solve for c (thread j holds E row j)
    float erow[MM];
#pragma unroll
    for (int q = 0; q < 8; ++q) {
        float4 v = *(const float4*)&sE[j * MM + q * 4];
        erow[q * 4 + 0] = v.x; erow[q * 4 + 1] = v.y;
        erow[q * 4 + 2] = v.z; erow[q * 4 + 3] = v.w;
    }
    float c_own = 0.0f;
#pragma unroll
    for (int i = 0; i < MM; ++i) {
        float contrib = (j < i) ? c_own * erow[i] : 0.0f;
#pragma unroll
        for (int off = 16; off > 0; off >>= 1)
            contrib += __shfl_xor_sync(0xffffffffu, contrib, off);
        const float ri = __shfl_sync(0xffffffffu, r_own, i);
        const float ai = __shfl_sync(0xffffffffu, a_own, i);
        const float vi = __shfl_sync(0xffffffffu, v_own, i);
        const float ci = ai - ri * (g * vi + contrib);
        if (j == i) c_own = ci;
    }

    gya[b * MM + j] = g * a_own;
    gcc[b * MM + j] = c_own;
    if (j == 0) gg[b] = g;
}

// ---------------- K3: out = g frc + sum (g a_j) y_j - sum c_i s_i --------
__global__ __launch_bounds__(256)
void k3_out(const float* __restrict__ S, const float* __restrict__ Y,
            const float* __restrict__ FRC, float* __restrict__ OUT) {
    __shared__ float sya[MM];
    __shared__ float scc[MM];
    __shared__ float sg[1];

    const int b  = blockIdx.x >> 3;
    const int ch = blockIdx.x & 7;
    const int tid = threadIdx.x;

    if (tid < MM) { sya[tid] = gya[b * MM + tid]; scc[tid] = gcc[b * MM + tid]; }
    if (tid == MM) sg[0] = gg[b];
    __syncthreads();

    const size_t d0 = (size_t)ch * CH3 + tid * 4;
    const float g = sg[0];
    float4 f = *(const float4*)(FRC + (size_t)b * DD + d0);
    u64 acc0 = pk2(g * f.x, g * f.y);
    u64 acc1 = pk2(g * f.z, g * f.w);

#pragma unroll
    for (int j = 0; j < MM; ++j) {
        ulonglong2 yv = *(const ulonglong2*)(Y + ((size_t)j * BB + b) * DD + d0);
        const float cv = sya[j];
        const u64 cc = pk2(cv, cv);
        acc0 = fma2(cc, yv.x, acc0);
        acc1 = fma2(cc, yv.y, acc1);
    }
#pragma unroll
    for (int i = 0; i < MM; ++i) {
        ulonglong2 sv = *(const ulonglong2*)(S + ((size_t)i * BB + b) * DD + d0);
        const float cv = -scc[i];
        const u64 cc = pk2(cv, cv);
        acc0 = fma2(cc, sv.x, acc0);
        acc1 = fma2(cc, sv.y, acc1);
    }

    float2 o0 = upk2(acc0), o1 = upk2(acc1);
    float4 o; o.x = o0.x; o.y = o0.y; o.z = o1.x; o.w = o1.y;
    *(float4*)(OUT + (size_t)b * DD + d0) = o;
}

// ---------------- launch ----------------
extern "C" void kernel_launch(void* const* d_in, const int* in_sizes, int n_in,
                              void* d_out, int out_size) {
    const float* S   = (const float*)d_in[0];  // (M, B, D)
    const float* Y   = (const float*)d_in[1];  // (M, B, D)
    const float* FRC = (const float*)d_in[2];  // (B, D)
    float* OUT = (float*)d_out;                // (B, D)

    static bool attr_set = false;
    if (!attr_set) {
        cudaFuncSetAttribute(k1_gram,
                             cudaFuncAttributeMaxDynamicSharedMemorySize,
                             K1_SMEM);
        attr_set = true;
    }

    k1_gram<<<BB * NG, 256, K1_SMEM>>>(S, Y, FRC);
    k2_solve<<<BB, 256>>>();
    k3_out<<<BB * NCH3, 256>>>(S, Y, FRC, OUT);
}